// round 6
// baseline (speedup 1.0000x reference)
#include <cuda_runtime.h>
#include <math.h>

// Problem constants
#define BHALF 2048          // b
#define NROWS 4096          // 2b
#define D1    4096
#define D2    2048
#define NT    64            // NROWS / BM tile grid dim
#define BM    64            // tile M = tile N
#define BK    16
#define NTILES (NT * (NT + 1) / 2)   // 2080 upper-triangular block tiles

// ---------------- device scratch (no allocations allowed) ----------------
__device__ float  g_sq1[NROWS];
__device__ float  g_sq2[NROWS];
__device__ float  g_cs1[D1];
__device__ float  g_cs2[D2];
__device__ double g_S1, g_S2, g_T1, g_T2;
__device__ float  g_c1, g_c2;          // 1/(16*bw)
__device__ double g_acc;

// ---------------- init: zero all accumulators ----------------
__global__ void init_kernel() {
    int idx = blockIdx.x * blockDim.x + threadIdx.x;
    if (idx < D1) g_cs1[idx] = 0.f;
    if (idx < D2) g_cs2[idx] = 0.f;
    if (idx == 0) {
        g_S1 = 0.0; g_S2 = 0.0; g_T1 = 0.0; g_T2 = 0.0; g_acc = 0.0;
    }
}

// ---------------- row squared norms + S = sum of norms ----------------
// grid: 8192 blocks (4096 rows for matrix1, 4096 for matrix2), 128 threads
__global__ void rowsq_kernel(const float* __restrict__ z1s, const float* __restrict__ z1t,
                             const float* __restrict__ z2s, const float* __restrict__ z2t) {
    int task  = blockIdx.x;
    int which = task >> 12;           // 0 -> matrix1, 1 -> matrix2
    int row   = task & (NROWS - 1);
    const float* p;
    int d4;
    if (which == 0) {
        d4 = D1 / 4;
        p = (row < BHALF) ? z1s + (size_t)row * D1 : z1t + (size_t)(row - BHALF) * D1;
    } else {
        d4 = D2 / 4;
        p = (row < BHALF) ? z2s + (size_t)row * D2 : z2t + (size_t)(row - BHALF) * D2;
    }
    const float4* p4 = (const float4*)p;
    float s = 0.f;
    for (int k = threadIdx.x; k < d4; k += blockDim.x) {
        float4 v = p4[k];
        s += v.x * v.x + v.y * v.y + v.z * v.z + v.w * v.w;
    }
    __shared__ float sh[4];
    #pragma unroll
    for (int o = 16; o > 0; o >>= 1) s += __shfl_down_sync(0xffffffffu, s, o);
    if ((threadIdx.x & 31) == 0) sh[threadIdx.x >> 5] = s;
    __syncthreads();
    if (threadIdx.x == 0) {
        float t = sh[0] + sh[1] + sh[2] + sh[3];
        if (which == 0) { g_sq1[row] = t; atomicAdd(&g_S1, (double)t); }
        else            { g_sq2[row] = t; atomicAdd(&g_S2, (double)t); }
    }
}

// ---------------- partial column sums (for ||sum_i x_i||^2) ----------------
// grid: 24 col-blocks * 16 row-chunks; 256 threads. Coalesced column traversal.
__global__ void colsum_partial(const float* __restrict__ z1s, const float* __restrict__ z1t,
                               const float* __restrict__ z2s, const float* __restrict__ z2t) {
    const int colBlocks = (D1 + D2) / 256;     // 24
    int cb    = blockIdx.x % colBlocks;
    int chunk = blockIdx.x / colBlocks;        // 0..15, 256 rows each over concat
    int idx   = cb * 256 + threadIdx.x;
    int r0    = chunk * 256;
    float cs = 0.f;
    if (idx < D1) {
        const float* p = (r0 < BHALF) ? z1s + (size_t)r0 * D1 + idx
                                      : z1t + (size_t)(r0 - BHALF) * D1 + idx;
        #pragma unroll 4
        for (int r = 0; r < 256; r++) cs += p[(size_t)r * D1];
        atomicAdd(&g_cs1[idx], cs);
    } else {
        int k = idx - D1;
        const float* p = (r0 < BHALF) ? z2s + (size_t)r0 * D2 + k
                                      : z2t + (size_t)(r0 - BHALF) * D2 + k;
        #pragma unroll 4
        for (int r = 0; r < 256; r++) cs += p[(size_t)r * D2];
        atomicAdd(&g_cs2[k], cs);
    }
}

// ---------------- T = sum of squared column sums ----------------
// grid: 24 blocks * 256 (first 16 blocks -> matrix1, rest -> matrix2)
__global__ void tsum_kernel() {
    int idx = blockIdx.x * blockDim.x + threadIdx.x;
    double v;
    double* dst;
    if (idx < D1) { float c = g_cs1[idx];       v = (double)c * c; dst = &g_T1; }
    else          { float c = g_cs2[idx - D1];  v = (double)c * c; dst = &g_T2; }
    #pragma unroll
    for (int o = 16; o > 0; o >>= 1)
        v += __shfl_down_sync(0xffffffffu, v, o);
    if ((threadIdx.x & 31) == 0) atomicAdd(dst, v);
}

// ---------------- bandwidth: bw = sum(l2)/(n^2-n)/4 ; store 1/(16 bw) -----
__global__ void bw_kernel() {
    double nn = (double)NROWS * (double)(NROWS - 1);
    double sum1 = 2.0 * (double)NROWS * g_S1 - 2.0 * g_T1;
    double sum2 = 2.0 * (double)NROWS * g_S2 - 2.0 * g_T2;
    double bw1 = sum1 / nn / 4.0;
    double bw2 = sum2 / nn / 4.0;
    g_c1 = (float)(1.0 / (16.0 * bw1));
    g_c2 = (float)(1.0 / (16.0 * bw2));
}

// ---------------- main fused kernel: symmetric dual-Gram + JMMD epilogue ---
__global__ __launch_bounds__(256, 2)
void jmmd_main(const float* __restrict__ z1s, const float* __restrict__ z1t,
               const float* __restrict__ z2s, const float* __restrict__ z2t) {
    // map linear tile id -> (I, J) with I <= J
    int t = blockIdx.x;
    int I = 0, rem = t;
    while (rem >= NT - I) { rem -= NT - I; I++; }
    int J = I + rem;

    __shared__ float As[BK][BM + 4];
    __shared__ float Bs[BK][BM + 4];
    __shared__ float red[8];

    int tid = threadIdx.x;
    int loadRow = tid >> 2;            // 0..63
    int loadK4  = (tid & 3) << 2;      // 0,4,8,12
    int tx = tid & 15, ty = tid >> 4;  // 16x16 threads, 4x4 microtile each

    float acc1[4][4], acc2[4][4];
    #pragma unroll
    for (int m = 0; m < 4; m++)
        #pragma unroll
        for (int n = 0; n < 4; n++) { acc1[m][n] = 0.f; acc2[m][n] = 0.f; }

    int ra = I * BM + loadRow;
    int rb = J * BM + loadRow;

    // ---- phase 1: G1 over D1 ----
    {
        const float* ap = (ra < BHALF) ? z1s + (size_t)ra * D1 : z1t + (size_t)(ra - BHALF) * D1;
        const float* bp = (rb < BHALF) ? z1s + (size_t)rb * D1 : z1t + (size_t)(rb - BHALF) * D1;
        for (int kc = 0; kc < D1; kc += BK) {
            float4 av = *(const float4*)(ap + kc + loadK4);
            float4 bv = *(const float4*)(bp + kc + loadK4);
            __syncthreads();
            As[loadK4 + 0][loadRow] = av.x; As[loadK4 + 1][loadRow] = av.y;
            As[loadK4 + 2][loadRow] = av.z; As[loadK4 + 3][loadRow] = av.w;
            Bs[loadK4 + 0][loadRow] = bv.x; Bs[loadK4 + 1][loadRow] = bv.y;
            Bs[loadK4 + 2][loadRow] = bv.z; Bs[loadK4 + 3][loadRow] = bv.w;
            __syncthreads();
            #pragma unroll
            for (int kk = 0; kk < BK; kk++) {
                float4 a  = *(const float4*)&As[kk][ty << 2];
                float4 bb = *(const float4*)&Bs[kk][tx << 2];
                acc1[0][0] += a.x * bb.x; acc1[0][1] += a.x * bb.y;
                acc1[0][2] += a.x * bb.z; acc1[0][3] += a.x * bb.w;
                acc1[1][0] += a.y * bb.x; acc1[1][1] += a.y * bb.y;
                acc1[1][2] += a.y * bb.z; acc1[1][3] += a.y * bb.w;
                acc1[2][0] += a.z * bb.x; acc1[2][1] += a.z * bb.y;
                acc1[2][2] += a.z * bb.z; acc1[2][3] += a.z * bb.w;
                acc1[3][0] += a.w * bb.x; acc1[3][1] += a.w * bb.y;
                acc1[3][2] += a.w * bb.z; acc1[3][3] += a.w * bb.w;
            }
        }
    }
    // ---- phase 2: G2 over D2 ----
    {
        const float* ap = (ra < BHALF) ? z2s + (size_t)ra * D2 : z2t + (size_t)(ra - BHALF) * D2;
        const float* bp = (rb < BHALF) ? z2s + (size_t)rb * D2 : z2t + (size_t)(rb - BHALF) * D2;
        for (int kc = 0; kc < D2; kc += BK) {
            float4 av = *(const float4*)(ap + kc + loadK4);
            float4 bv = *(const float4*)(bp + kc + loadK4);
            __syncthreads();
            As[loadK4 + 0][loadRow] = av.x; As[loadK4 + 1][loadRow] = av.y;
            As[loadK4 + 2][loadRow] = av.z; As[loadK4 + 3][loadRow] = av.w;
            Bs[loadK4 + 0][loadRow] = bv.x; Bs[loadK4 + 1][loadRow] = bv.y;
            Bs[loadK4 + 2][loadRow] = bv.z; Bs[loadK4 + 3][loadRow] = bv.w;
            __syncthreads();
            #pragma unroll
            for (int kk = 0; kk < BK; kk++) {
                float4 a  = *(const float4*)&As[kk][ty << 2];
                float4 bb = *(const float4*)&Bs[kk][tx << 2];
                acc2[0][0] += a.x * bb.x; acc2[0][1] += a.x * bb.y;
                acc2[0][2] += a.x * bb.z; acc2[0][3] += a.x * bb.w;
                acc2[1][0] += a.y * bb.x; acc2[1][1] += a.y * bb.y;
                acc2[1][2] += a.y * bb.z; acc2[1][3] += a.y * bb.w;
                acc2[2][0] += a.z * bb.x; acc2[2][1] += a.z * bb.y;
                acc2[2][2] += a.z * bb.z; acc2[2][3] += a.z * bb.w;
                acc2[3][0] += a.w * bb.x; acc2[3][1] += a.w * bb.y;
                acc2[3][2] += a.w * bb.z; acc2[3][3] += a.w * bb.w;
            }
        }
    }

    // ---- epilogue: multi-bandwidth Gaussian product * index weight ----
    const float c1 = g_c1, c2 = g_c2;
    const float OFFW = (float)(1.0 / ((double)BHALF * (double)(BHALF - 1)));
    const float NEGW = (float)(-1.0 / ((double)BHALF * (double)BHALF));
    int gi0 = I * BM + (ty << 2);
    int gj0 = J * BM + (tx << 2);

    float sq1i[4], sq1j[4], sq2i[4], sq2j[4];
    #pragma unroll
    for (int m = 0; m < 4; m++) {
        sq1i[m] = g_sq1[gi0 + m]; sq1j[m] = g_sq1[gj0 + m];
        sq2i[m] = g_sq2[gi0 + m]; sq2j[m] = g_sq2[gj0 + m];
    }

    float local = 0.f;
    #pragma unroll
    for (int m = 0; m < 4; m++) {
        #pragma unroll
        for (int n = 0; n < 4; n++) {
            int gi = gi0 + m, gj = gj0 + n;
            float l2a = fmaxf(sq1i[m] + sq1j[n] - 2.f * acc1[m][n], 0.f);
            float e = __expf(-l2a * c1);           // exp(-l2/(16 bw))
            float k1 = e;                           // e + e^2 + e^4 + e^8 + e^16
            e *= e; k1 += e; e *= e; k1 += e; e *= e; k1 += e; e *= e; k1 += e;
            float l2b = fmaxf(sq2i[m] + sq2j[n] - 2.f * acc2[m][n], 0.f);
            e = __expf(-l2b * c2);
            float k2 = e;
            e *= e; k2 += e; e *= e; k2 += e; e *= e; k2 += e; e *= e; k2 += e;
            bool within = (gi < BHALF) == (gj < BHALF);
            float w = within ? ((gi == gj) ? 0.f : OFFW) : NEGW;
            local += k1 * k2 * w;
        }
    }
    if (I != J) local *= 2.f;   // symmetric off-diagonal tile counted twice

    // block reduce -> one double atomic per block
    #pragma unroll
    for (int o = 16; o > 0; o >>= 1)
        local += __shfl_down_sync(0xffffffffu, local, o);
    if ((tid & 31) == 0) red[tid >> 5] = local;
    __syncthreads();
    if (tid == 0) {
        float s = 0.f;
        #pragma unroll
        for (int wgi = 0; wgi < 8; wgi++) s += red[wgi];
        atomicAdd(&g_acc, (double)s);
    }
}

// ---------------- finalize ----------------
__global__ void finalize_kernel(float* out) {
    out[0] = (float)(g_acc + 2.0 / (double)(BHALF - 1));
}

extern "C" void kernel_launch(void* const* d_in, const int* in_sizes, int n_in,
                              void* d_out, int out_size) {
    const float* z1s = (const float*)d_in[0];
    const float* z1t = (const float*)d_in[1];
    const float* z2s = (const float*)d_in[2];
    const float* z2t = (const float*)d_in[3];
    float* out = (float*)d_out;

    init_kernel<<<(D1 + 255) / 256, 256>>>();
    rowsq_kernel<<<2 * NROWS, 128>>>(z1s, z1t, z2s, z2t);
    colsum_partial<<<((D1 + D2) / 256) * 16, 256>>>(z1s, z1t, z2s, z2t);
    tsum_kernel<<<(D1 + D2) / 256, 256>>>();
    bw_kernel<<<1, 1>>>();
    jmmd_main<<<NTILES, 256>>>(z1s, z1t, z2s, z2t);
    finalize_kernel<<<1, 1>>>(out);
}

// round 8
// speedup vs baseline: 1.8104x; 1.8104x over previous
#include <cuda_runtime.h>
#include <cstdint>
#include <math.h>

// ---------------- problem constants ----------------
#define BHALF 2048
#define NROWS 4096
#define D1    4096
#define D2    2048

// ---------------- tiling ----------------
#define TILE  128                   // CTA tile: 128 x 128
#define BK    32                    // k per chunk (floats)
#define NSTAGE 3
#define NCH1  (D1 / BK)             // 128
#define NCH2  (D2 / BK)             // 64
#define NCHT  (NCH1 + NCH2)         // 192
#define GRID_TILES (32 * 33 / 2)    // 528 triangular tiles

// smem layout (bytes). Operand rows padded to 144B (9 x 16B -> ldmatrix conflict-free)
#define RSB       144u
#define ATILE_B   (128u * RSB)            // 18432
#define STAGE_B   (2u * ATILE_B)          // 36864 per stage (A + B)
#define SM_A(s)   ((s) * STAGE_B)
#define SM_B(s)   (SM_A(s) + ATILE_B)
#define STAGE_OFF (NSTAGE * STAGE_B)      // 110592 : G1 staging area
#define G1_STRIDE 132u                    // floats
#define RED_OFF   (STAGE_OFF + 128u * G1_STRIDE * 4u)   // 178176
#define SMEM_TOTAL (RED_OFF + 64u)

// ---------------- device scratch ----------------
__device__ float  g_sq1[NROWS];
__device__ float  g_sq2[NROWS];
__device__ float  g_cs1[D1];
__device__ float  g_cs2[D2];
__device__ double g_S1, g_S2, g_T1, g_T2;
__device__ float  g_c1, g_c2;
__device__ double g_acc;

// ---------------- asm helpers (plain sm_80-level PTX only) ----------------
__device__ __forceinline__ uint32_t smem_u32(const void* p) {
    uint32_t a;
    asm("{ .reg .u64 t; cvta.to.shared.u64 t, %1; cvt.u32.u64 %0, t; }" : "=r"(a) : "l"(p));
    return a;
}
#define CP_ASYNC16(dst, src) \
    asm volatile("cp.async.cg.shared.global [%0], [%1], 16;" :: "r"(dst), "l"(src))
#define CP_COMMIT()  asm volatile("cp.async.commit_group;" ::: "memory")
#define CP_WAIT1()   asm volatile("cp.async.wait_group 1;" ::: "memory")

#define LDSM4(r, addr) \
    asm volatile("ldmatrix.sync.aligned.m8n8.x4.shared.b16 {%0,%1,%2,%3}, [%4];" \
        : "=r"((r)[0]), "=r"((r)[1]), "=r"((r)[2]), "=r"((r)[3]) : "r"(addr))

#define MMA_TF32(d, a, b) \
    asm volatile("mma.sync.aligned.m16n8k8.row.col.f32.tf32.tf32.f32 " \
        "{%0,%1,%2,%3}, {%4,%5,%6,%7}, {%8,%9}, {%0,%1,%2,%3};" \
        : "+f"((d)[0]), "+f"((d)[1]), "+f"((d)[2]), "+f"((d)[3]) \
        : "r"((a)[0]), "r"((a)[1]), "r"((a)[2]), "r"((a)[3]), \
          "r"((b)[0]), "r"((b)[1]))

// ---------------- prepass kernels (unchanged, proven) ----------------
__global__ void init_kernel() {
    int idx = blockIdx.x * blockDim.x + threadIdx.x;
    if (idx < D1) g_cs1[idx] = 0.f;
    if (idx < D2) g_cs2[idx] = 0.f;
    if (idx == 0) { g_S1 = 0.0; g_S2 = 0.0; g_T1 = 0.0; g_T2 = 0.0; g_acc = 0.0; }
}

__global__ void rowsq_kernel(const float* __restrict__ z1s, const float* __restrict__ z1t,
                             const float* __restrict__ z2s, const float* __restrict__ z2t) {
    int task  = blockIdx.x;
    int which = task >> 12;
    int row   = task & (NROWS - 1);
    const float* p;
    int d4;
    if (which == 0) {
        d4 = D1 / 4;
        p = (row < BHALF) ? z1s + (size_t)row * D1 : z1t + (size_t)(row - BHALF) * D1;
    } else {
        d4 = D2 / 4;
        p = (row < BHALF) ? z2s + (size_t)row * D2 : z2t + (size_t)(row - BHALF) * D2;
    }
    const float4* p4 = (const float4*)p;
    float s = 0.f;
    for (int k = threadIdx.x; k < d4; k += blockDim.x) {
        float4 v = p4[k];
        s += v.x * v.x + v.y * v.y + v.z * v.z + v.w * v.w;
    }
    __shared__ float sh[4];
    #pragma unroll
    for (int o = 16; o > 0; o >>= 1) s += __shfl_down_sync(0xffffffffu, s, o);
    if ((threadIdx.x & 31) == 0) sh[threadIdx.x >> 5] = s;
    __syncthreads();
    if (threadIdx.x == 0) {
        float t = sh[0] + sh[1] + sh[2] + sh[3];
        if (which == 0) { g_sq1[row] = t; atomicAdd(&g_S1, (double)t); }
        else            { g_sq2[row] = t; atomicAdd(&g_S2, (double)t); }
    }
}

__global__ void colsum_partial(const float* __restrict__ z1s, const float* __restrict__ z1t,
                               const float* __restrict__ z2s, const float* __restrict__ z2t) {
    const int colBlocks = (D1 + D2) / 256;
    int cb    = blockIdx.x % colBlocks;
    int chunk = blockIdx.x / colBlocks;
    int idx   = cb * 256 + threadIdx.x;
    int r0    = chunk * 256;
    float cs = 0.f;
    if (idx < D1) {
        const float* p = (r0 < BHALF) ? z1s + (size_t)r0 * D1 + idx
                                      : z1t + (size_t)(r0 - BHALF) * D1 + idx;
        #pragma unroll 4
        for (int r = 0; r < 256; r++) cs += p[(size_t)r * D1];
        atomicAdd(&g_cs1[idx], cs);
    } else {
        int k = idx - D1;
        const float* p = (r0 < BHALF) ? z2s + (size_t)r0 * D2 + k
                                      : z2t + (size_t)(r0 - BHALF) * D2 + k;
        #pragma unroll 4
        for (int r = 0; r < 256; r++) cs += p[(size_t)r * D2];
        atomicAdd(&g_cs2[k], cs);
    }
}

__global__ void tsum_kernel() {
    int idx = blockIdx.x * blockDim.x + threadIdx.x;
    double v;
    double* dst;
    if (idx < D1) { float c = g_cs1[idx];       v = (double)c * c; dst = &g_T1; }
    else          { float c = g_cs2[idx - D1];  v = (double)c * c; dst = &g_T2; }
    #pragma unroll
    for (int o = 16; o > 0; o >>= 1)
        v += __shfl_down_sync(0xffffffffu, v, o);
    if ((threadIdx.x & 31) == 0) atomicAdd(dst, v);
}

__global__ void bw_kernel() {
    double nn = (double)NROWS * (double)(NROWS - 1);
    double sum1 = 2.0 * (double)NROWS * g_S1 - 2.0 * g_T1;
    double sum2 = 2.0 * (double)NROWS * g_S2 - 2.0 * g_T2;
    g_c1 = (float)(1.0 / (16.0 * (sum1 / nn / 4.0)));
    g_c2 = (float)(1.0 / (16.0 * (sum2 / nn / 4.0)));
}

// ---------------- main kernel: tf32 mma.sync dual-Gram + fused JMMD ----------------
__global__ __launch_bounds__(256, 1)
void jmmd_mma(const float* __restrict__ z1s, const float* __restrict__ z1t,
              const float* __restrict__ z2s, const float* __restrict__ z2t) {
    extern __shared__ char smem[];
    uint32_t sb = smem_u32(smem);
    int tid = threadIdx.x, wid = tid >> 5, lane = tid & 31;
    int g = lane >> 2, tg = lane & 3;

    // triangular unrank: tile (I, J), I >= J, both over 32 tiles of 128
    int rem = blockIdx.x, I = 0;
    while (rem >= I + 1) { rem -= I + 1; I++; }
    int J = rem;
    int Ibase = I * TILE, Jbase = J * TILE;

    const float* a1 = (Ibase < BHALF) ? z1s + (size_t)Ibase * D1 : z1t + (size_t)(Ibase - BHALF) * D1;
    const float* b1 = (Jbase < BHALF) ? z1s + (size_t)Jbase * D1 : z1t + (size_t)(Jbase - BHALF) * D1;
    const float* a2 = (Ibase < BHALF) ? z2s + (size_t)Ibase * D2 : z2t + (size_t)(Ibase - BHALF) * D2;
    const float* b2 = (Jbase < BHALF) ? z2s + (size_t)Jbase * D2 : z2t + (size_t)(Jbase - BHALF) * D2;

    int m0 = (wid & 3) * 32;        // warp sub-tile 32 (M) x 64 (N)
    int n0 = (wid >> 2) * 64;

    float acc[2][8][4];
    #pragma unroll
    for (int mt = 0; mt < 2; mt++)
        #pragma unroll
        for (int nt = 0; nt < 8; nt++)
            #pragma unroll
            for (int r = 0; r < 4; r++) acc[mt][nt][r] = 0.f;

    // ---- loader: 8 x 16B cp.async per thread per chunk ----
    auto issue = [&](int c) {
        const float *Ap, *Bp; int Dk, kk;
        if (c < NCH1) { Ap = a1; Bp = b1; Dk = D1; kk = c * BK; }
        else          { Ap = a2; Bp = b2; Dk = D2; kk = (c - NCH1) * BK; }
        uint32_t sA = sb + SM_A(c % NSTAGE), sB = sb + SM_B(c % NSTAGE);
        #pragma unroll
        for (int i = 0; i < 4; i++) {
            int seg = tid + i * 256;           // 1024 segs each of A, B
            int row = seg >> 3, sg = seg & 7;
            uint32_t so = (uint32_t)row * RSB + (uint32_t)sg * 16u;
            CP_ASYNC16(sA + so, Ap + (size_t)row * Dk + kk + sg * 4);
            CP_ASYNC16(sB + so, Bp + (size_t)row * Dk + kk + sg * 4);
        }
        CP_COMMIT();
    };

    // ---- compute one BK=32 chunk from staged buffers ----
    auto compute = [&](int c) {
        uint32_t bufA = sb + SM_A(c % NSTAGE), bufB = sb + SM_B(c % NSTAGE);
        #pragma unroll
        for (int ks = 0; ks < 4; ks++) {
            uint32_t a[2][4];
            #pragma unroll
            for (int mt = 0; mt < 2; mt++) {
                // quadrants: lanes 0-15 rows (colgrp0), 16-31 same rows colgrp1
                uint32_t row = (uint32_t)(m0 + mt * 16 + (lane & 15));
                uint32_t col = (uint32_t)(ks * 32 + ((lane >> 4) << 4));
                LDSM4(a[mt], bufA + row * RSB + col);
            }
            uint32_t b[8][2];
            #pragma unroll
            for (int np = 0; np < 4; np++) {   // pairs of n-tiles
                int q = lane >> 3;
                uint32_t row = (uint32_t)(n0 + np * 16 + (lane & 7) + ((q >> 1) << 3));
                uint32_t col = (uint32_t)(ks * 32 + ((q & 1) << 4));
                uint32_t r4[4];
                LDSM4(r4, bufB + row * RSB + col);
                b[2 * np][0] = r4[0]; b[2 * np][1] = r4[1];
                b[2 * np + 1][0] = r4[2]; b[2 * np + 1][1] = r4[3];
            }
            #pragma unroll
            for (int mt = 0; mt < 2; mt++)
                #pragma unroll
                for (int nt = 0; nt < 8; nt++)
                    MMA_TF32(acc[mt][nt], a[mt], b[nt]);
        }
    };

    // ---- pipelined main loop ----
    issue(0); issue(1);
    float* stage = (float*)(smem + STAGE_OFF);
    for (int c = 0; c < NCHT; c++) {
        CP_WAIT1();
        __syncthreads();
        if (c + 2 < NCHT) issue(c + 2);
        compute(c);
        if (c == NCH1 - 1) {
            // dump G1 accumulators to warp-private smem region, reset accs
            #pragma unroll
            for (int mt = 0; mt < 2; mt++)
                #pragma unroll
                for (int nt = 0; nt < 8; nt++) {
                    int r0 = m0 + mt * 16 + g, cc = n0 + nt * 8 + 2 * tg;
                    *(float2*)&stage[(size_t)r0 * G1_STRIDE + cc] =
                        make_float2(acc[mt][nt][0], acc[mt][nt][1]);
                    *(float2*)&stage[(size_t)(r0 + 8) * G1_STRIDE + cc] =
                        make_float2(acc[mt][nt][2], acc[mt][nt][3]);
                    acc[mt][nt][0] = 0.f; acc[mt][nt][1] = 0.f;
                    acc[mt][nt][2] = 0.f; acc[mt][nt][3] = 0.f;
                }
        }
    }

    // ---- fused epilogue: G1 from smem, G2 in regs ----
    const float c1 = g_c1, c2 = g_c2;
    const float OFFW = (float)(1.0 / ((double)BHALF * (double)(BHALF - 1)));
    const float NEGW = (float)(-1.0 / ((double)BHALF * (double)BHALF));

    float s1i[4], s2i[4];                 // (mt, pr) row halves
    #pragma unroll
    for (int mt = 0; mt < 2; mt++)
        #pragma unroll
        for (int pr = 0; pr < 2; pr++) {
            int gi = Ibase + m0 + mt * 16 + pr * 8 + g;
            s1i[mt * 2 + pr] = g_sq1[gi];
            s2i[mt * 2 + pr] = g_sq2[gi];
        }
    float s1j[16], s2j[16];               // (nt, e) columns
    #pragma unroll
    for (int nt = 0; nt < 8; nt++)
        #pragma unroll
        for (int e = 0; e < 2; e++) {
            int gj = Jbase + n0 + nt * 8 + 2 * tg + e;
            s1j[nt * 2 + e] = g_sq1[gj];
            s2j[nt * 2 + e] = g_sq2[gj];
        }

    float local = 0.f;
    #pragma unroll
    for (int mt = 0; mt < 2; mt++)
        #pragma unroll
        for (int pr = 0; pr < 2; pr++) {
            int gi = Ibase + m0 + mt * 16 + pr * 8 + g;
            #pragma unroll
            for (int nt = 0; nt < 8; nt++) {
                int r0 = m0 + mt * 16 + pr * 8 + g, cc = n0 + nt * 8 + 2 * tg;
                float2 g1v = *(float2*)&stage[(size_t)r0 * G1_STRIDE + cc];
                #pragma unroll
                for (int e = 0; e < 2; e++) {
                    int gj = Jbase + cc + e;
                    float gram1 = e ? g1v.y : g1v.x;
                    float gram2 = acc[mt][nt][pr * 2 + e];
                    float l2a = fmaxf(s1i[mt * 2 + pr] + s1j[nt * 2 + e] - 2.f * gram1, 0.f);
                    float ex = __expf(-l2a * c1);
                    float k1 = ex; ex *= ex; k1 += ex; ex *= ex; k1 += ex;
                    ex *= ex; k1 += ex; ex *= ex; k1 += ex;
                    float l2b = fmaxf(s2i[mt * 2 + pr] + s2j[nt * 2 + e] - 2.f * gram2, 0.f);
                    ex = __expf(-l2b * c2);
                    float k2 = ex; ex *= ex; k2 += ex; ex *= ex; k2 += ex;
                    ex *= ex; k2 += ex; ex *= ex; k2 += ex;
                    if (gi > gj) {
                        float w = ((gi < BHALF) == (gj < BHALF)) ? OFFW : NEGW;
                        local += 2.f * w * k1 * k2;
                    }
                }
            }
        }

    #pragma unroll
    for (int o = 16; o > 0; o >>= 1) local += __shfl_down_sync(0xffffffffu, local, o);
    float* red = (float*)(smem + RED_OFF);
    if (lane == 0) red[wid] = local;
    __syncthreads();
    if (tid == 0) {
        float ssum = 0.f;
        #pragma unroll
        for (int wgi = 0; wgi < 8; wgi++) ssum += red[wgi];
        atomicAdd(&g_acc, (double)ssum);
    }
}

// ---------------- finalize ----------------
__global__ void finalize_kernel(float* out) {
    out[0] = (float)(g_acc + 2.0 / (double)(BHALF - 1));
}

extern "C" void kernel_launch(void* const* d_in, const int* in_sizes, int n_in,
                              void* d_out, int out_size) {
    const float* z1s = (const float*)d_in[0];
    const float* z1t = (const float*)d_in[1];
    const float* z2s = (const float*)d_in[2];
    const float* z2t = (const float*)d_in[3];
    float* out = (float*)d_out;

    cudaFuncSetAttribute(jmmd_mma, cudaFuncAttributeMaxDynamicSharedMemorySize, SMEM_TOTAL);

    init_kernel<<<(D1 + 255) / 256, 256>>>();
    rowsq_kernel<<<2 * NROWS, 128>>>(z1s, z1t, z2s, z2t);
    colsum_partial<<<((D1 + D2) / 256) * 16, 256>>>(z1s, z1t, z2s, z2t);
    tsum_kernel<<<(D1 + D2) / 256, 256>>>();
    bw_kernel<<<1, 1>>>();
    jmmd_mma<<<GRID_TILES, 256, SMEM_TOTAL>>>(z1s, z1t, z2s, z2t);
    finalize_kernel<<<1, 1>>>(out);
}

// round 10
// speedup vs baseline: 2.2252x; 1.2291x over previous
#include <cuda_runtime.h>
#include <cstdint>
#include <math.h>

// ---------------- problem constants ----------------
#define BHALF 2048
#define NROWS 4096
#define D1    4096
#define D2    2048

// ---------------- tiling ----------------
#define TILE  128                   // CTA tile: 128 x 128
#define BK    32                    // k per chunk (floats) = 128B per row
#define NSTAGE 3
#define NCH1  (D1 / BK)             // 128
#define NCH2  (D2 / BK)             // 64
#define NCHT  (NCH1 + NCH2)         // 192
#define GRID_TILES (32 * 33 / 2)    // 528 triangular tiles

// smem layout (bytes). Operand rows padded to 144B (9 x 16B -> ldmatrix conflict-free)
#define RSB       144u
#define ATILE_B   (128u * RSB)            // 18432
#define STAGE_B   (2u * ATILE_B)          // 36864 per stage (A + B)
#define MB_FULL(s) (16u + 8u*(s))
#define SM_A(s)   (1024u + (s) * STAGE_B)
#define SM_B(s)   (SM_A(s) + ATILE_B)
#define STAGE_OFF (1024u + NSTAGE * STAGE_B)            // 111616 : G1 staging
#define G1_STRIDE 132u                                  // floats
#define RED_OFF   (STAGE_OFF + 128u * G1_STRIDE * 4u)   // 179200
#define SMEM_TOTAL (RED_OFF + 64u)
#define CHUNK_BYTES 32768u          // 256 rows x 128B per chunk

// ---------------- device scratch ----------------
__device__ float  g_sq1[NROWS];
__device__ float  g_sq2[NROWS];
__device__ float  g_cs1[D1];
__device__ float  g_cs2[D2];
__device__ double g_S1, g_S2, g_T1, g_T2;
__device__ float  g_c1, g_c2;
__device__ double g_acc;

// ---------------- asm helpers (baseline sm_90-level PTX only, no 'a' features) ----
__device__ __forceinline__ uint32_t smem_u32(const void* p) {
    uint32_t a;
    asm("{ .reg .u64 t; cvta.to.shared.u64 t, %1; cvt.u32.u64 %0, t; }" : "=r"(a) : "l"(p));
    return a;
}
__device__ __forceinline__ void mbar_init(uint32_t a, uint32_t cnt) {
    asm volatile("mbarrier.init.shared.b64 [%0], %1;" :: "r"(a), "r"(cnt) : "memory");
}
__device__ __forceinline__ void mbar_expect_tx(uint32_t a, uint32_t bytes) {
    asm volatile("mbarrier.arrive.expect_tx.shared.b64 _, [%0], %1;"
                 :: "r"(a), "r"(bytes) : "memory");
}
__device__ __forceinline__ void mbar_wait(uint32_t a, uint32_t parity) {
    uint32_t done;
    asm volatile("{\n\t.reg .pred p;\n\t"
        "mbarrier.try_wait.parity.acquire.cta.shared::cta.b64 p, [%1], %2;\n\t"
        "selp.b32 %0, 1, 0, p;\n\t}"
        : "=r"(done) : "r"(a), "r"(parity) : "memory");
    if (!done) {
        asm volatile("{\n\t.reg .pred P1;\n\t"
            "WL%=:\n\t"
            "mbarrier.try_wait.parity.acquire.cta.shared::cta.b64 P1, [%0], %1, 0x989680;\n\t"
            "@P1 bra.uni WD%=;\n\t"
            "bra.uni WL%=;\n\t"
            "WD%=:\n\t}"
            :: "r"(a), "r"(parity) : "memory");
    }
}
#define BULK_CP128(dst, src, mbar) \
    asm volatile("cp.async.bulk.shared::cluster.global.mbarrier::complete_tx::bytes " \
                 "[%0], [%1], %2, [%3];" \
                 :: "r"(dst), "l"(src), "r"(128u), "r"(mbar) : "memory")

#define LDSM4(r, addr) \
    asm volatile("ldmatrix.sync.aligned.m8n8.x4.shared.b16 {%0,%1,%2,%3}, [%4];" \
        : "=r"((r)[0]), "=r"((r)[1]), "=r"((r)[2]), "=r"((r)[3]) : "r"(addr))

#define MMA_TF32(d, a, b) \
    asm volatile("mma.sync.aligned.m16n8k8.row.col.f32.tf32.tf32.f32 " \
        "{%0,%1,%2,%3}, {%4,%5,%6,%7}, {%8,%9}, {%0,%1,%2,%3};" \
        : "+f"((d)[0]), "+f"((d)[1]), "+f"((d)[2]), "+f"((d)[3]) \
        : "r"((a)[0]), "r"((a)[1]), "r"((a)[2]), "r"((a)[3]), \
          "r"((b)[0]), "r"((b)[1]))

// ---------------- prepass kernels (unchanged, proven) ----------------
__global__ void init_kernel() {
    int idx = blockIdx.x * blockDim.x + threadIdx.x;
    if (idx < D1) g_cs1[idx] = 0.f;
    if (idx < D2) g_cs2[idx] = 0.f;
    if (idx == 0) { g_S1 = 0.0; g_S2 = 0.0; g_T1 = 0.0; g_T2 = 0.0; g_acc = 0.0; }
}

__global__ void rowsq_kernel(const float* __restrict__ z1s, const float* __restrict__ z1t,
                             const float* __restrict__ z2s, const float* __restrict__ z2t) {
    int task  = blockIdx.x;
    int which = task >> 12;
    int row   = task & (NROWS - 1);
    const float* p;
    int d4;
    if (which == 0) {
        d4 = D1 / 4;
        p = (row < BHALF) ? z1s + (size_t)row * D1 : z1t + (size_t)(row - BHALF) * D1;
    } else {
        d4 = D2 / 4;
        p = (row < BHALF) ? z2s + (size_t)row * D2 : z2t + (size_t)(row - BHALF) * D2;
    }
    const float4* p4 = (const float4*)p;
    float s = 0.f;
    for (int k = threadIdx.x; k < d4; k += blockDim.x) {
        float4 v = p4[k];
        s += v.x * v.x + v.y * v.y + v.z * v.z + v.w * v.w;
    }
    __shared__ float sh[4];
    #pragma unroll
    for (int o = 16; o > 0; o >>= 1) s += __shfl_down_sync(0xffffffffu, s, o);
    if ((threadIdx.x & 31) == 0) sh[threadIdx.x >> 5] = s;
    __syncthreads();
    if (threadIdx.x == 0) {
        float t = sh[0] + sh[1] + sh[2] + sh[3];
        if (which == 0) { g_sq1[row] = t; atomicAdd(&g_S1, (double)t); }
        else            { g_sq2[row] = t; atomicAdd(&g_S2, (double)t); }
    }
}

__global__ void colsum_partial(const float* __restrict__ z1s, const float* __restrict__ z1t,
                               const float* __restrict__ z2s, const float* __restrict__ z2t) {
    const int colBlocks = (D1 + D2) / 256;
    int cb    = blockIdx.x % colBlocks;
    int chunk = blockIdx.x / colBlocks;
    int idx   = cb * 256 + threadIdx.x;
    int r0    = chunk * 256;
    float cs = 0.f;
    if (idx < D1) {
        const float* p = (r0 < BHALF) ? z1s + (size_t)r0 * D1 + idx
                                      : z1t + (size_t)(r0 - BHALF) * D1 + idx;
        #pragma unroll 4
        for (int r = 0; r < 256; r++) cs += p[(size_t)r * D1];
        atomicAdd(&g_cs1[idx], cs);
    } else {
        int k = idx - D1;
        const float* p = (r0 < BHALF) ? z2s + (size_t)r0 * D2 + k
                                      : z2t + (size_t)(r0 - BHALF) * D2 + k;
        #pragma unroll 4
        for (int r = 0; r < 256; r++) cs += p[(size_t)r * D2];
        atomicAdd(&g_cs2[k], cs);
    }
}

__global__ void tsum_kernel() {
    int idx = blockIdx.x * blockDim.x + threadIdx.x;
    double v;
    double* dst;
    if (idx < D1) { float c = g_cs1[idx];       v = (double)c * c; dst = &g_T1; }
    else          { float c = g_cs2[idx - D1];  v = (double)c * c; dst = &g_T2; }
    #pragma unroll
    for (int o = 16; o > 0; o >>= 1)
        v += __shfl_down_sync(0xffffffffu, v, o);
    if ((threadIdx.x & 31) == 0) atomicAdd(dst, v);
}

__global__ void bw_kernel() {
    double nn = (double)NROWS * (double)(NROWS - 1);
    double sum1 = 2.0 * (double)NROWS * g_S1 - 2.0 * g_T1;
    double sum2 = 2.0 * (double)NROWS * g_S2 - 2.0 * g_T2;
    g_c1 = (float)(1.0 / (16.0 * (sum1 / nn / 4.0)));
    g_c2 = (float)(1.0 / (16.0 * (sum2 / nn / 4.0)));
}

// ---------------- main kernel: tf32 mma.sync dual-Gram, bulk-copy loads -----------
__global__ __launch_bounds__(256, 1)
void jmmd_mma(const float* __restrict__ z1s, const float* __restrict__ z1t,
              const float* __restrict__ z2s, const float* __restrict__ z2t) {
    extern __shared__ char smem[];
    uint32_t sb = smem_u32(smem);
    int tid = threadIdx.x, wid = tid >> 5, lane = tid & 31;
    int g = lane >> 2, tg = lane & 3;

    // triangular unrank: tile (I, J), I >= J, both over 32 tiles of 128
    int rem = blockIdx.x, I = 0;
    while (rem >= I + 1) { rem -= I + 1; I++; }
    int J = rem;
    int Ibase = I * TILE, Jbase = J * TILE;

    const float* a1 = (Ibase < BHALF) ? z1s + (size_t)Ibase * D1 : z1t + (size_t)(Ibase - BHALF) * D1;
    const float* b1 = (Jbase < BHALF) ? z1s + (size_t)Jbase * D1 : z1t + (size_t)(Jbase - BHALF) * D1;
    const float* a2 = (Ibase < BHALF) ? z2s + (size_t)Ibase * D2 : z2t + (size_t)(Ibase - BHALF) * D2;
    const float* b2 = (Jbase < BHALF) ? z2s + (size_t)Jbase * D2 : z2t + (size_t)(Jbase - BHALF) * D2;

    int m0 = (wid & 3) * 32;        // warp sub-tile 32 (M) x 64 (N)
    int n0 = (wid >> 2) * 64;

    float acc[2][8][4];
    #pragma unroll
    for (int mt = 0; mt < 2; mt++)
        #pragma unroll
        for (int nt = 0; nt < 8; nt++)
            #pragma unroll
            for (int r = 0; r < 4; r++) acc[mt][nt][r] = 0.f;

    // ---- mbarrier init: one full barrier per stage, single expect_tx arrival ----
    if (tid == 0) {
        #pragma unroll
        for (int s = 0; s < NSTAGE; s++) mbar_init(MB_FULL(s) + sb, 1);
    }
    __syncthreads();

    // ---- loader: ONE 128B cp.async.bulk per thread per chunk (row = tid) ----
    // rows 0..127 -> A tile, 128..255 -> B tile; tx-completion on stage barrier.
    int lrow  = tid & 127;
    int isB   = tid >> 7;
    uint32_t dstoff = (uint32_t)lrow * RSB;
    auto issue = [&](int c) {
        int s = c % NSTAGE;
        if (tid == 0) mbar_expect_tx(sb + MB_FULL(s), CHUNK_BYTES);
        const float* src;
        if (c < NCH1) src = (isB ? b1 : a1) + (size_t)lrow * D1 + c * BK;
        else          src = (isB ? b2 : a2) + (size_t)lrow * D2 + (c - NCH1) * BK;
        uint32_t dst = sb + (isB ? SM_B(s) : SM_A(s)) + dstoff;
        BULK_CP128(dst, src, sb + MB_FULL(s));
    };

    // ---- compute one BK=32 chunk from staged buffers (identical to R8) ----
    auto compute = [&](int c) {
        uint32_t bufA = sb + SM_A(c % NSTAGE), bufB = sb + SM_B(c % NSTAGE);
        #pragma unroll
        for (int ks = 0; ks < 4; ks++) {
            uint32_t a[2][4];
            #pragma unroll
            for (int mt = 0; mt < 2; mt++) {
                uint32_t row = (uint32_t)(m0 + mt * 16 + (lane & 15));
                uint32_t col = (uint32_t)(ks * 32 + ((lane >> 4) << 4));
                LDSM4(a[mt], bufA + row * RSB + col);
            }
            uint32_t b[8][2];
            #pragma unroll
            for (int np = 0; np < 4; np++) {
                int q = lane >> 3;
                uint32_t row = (uint32_t)(n0 + np * 16 + (lane & 7) + ((q >> 1) << 3));
                uint32_t col = (uint32_t)(ks * 32 + ((q & 1) << 4));
                uint32_t r4[4];
                LDSM4(r4, bufB + row * RSB + col);
                b[2 * np][0] = r4[0]; b[2 * np][1] = r4[1];
                b[2 * np + 1][0] = r4[2]; b[2 * np + 1][1] = r4[3];
            }
            #pragma unroll
            for (int mt = 0; mt < 2; mt++)
                #pragma unroll
                for (int nt = 0; nt < 8; nt++)
                    MMA_TF32(acc[mt][nt], a[mt], b[nt]);
        }
    };

    // ---- pipelined main loop ----
    issue(0); issue(1);
    float* stage = (float*)(smem + STAGE_OFF);
    int ph = 0, puse = 0;                         // parity of full[s] use for chunk c
    for (int c = 0; c < NCHT; c++) {
        int s = c % NSTAGE;
        mbar_wait(sb + MB_FULL(s), ph);
        if (++puse == NSTAGE) { puse = 0; ph ^= 1; }   // phase flips every NSTAGE chunks
        compute(c);
        if (c == NCH1 - 1) {
            // dump G1 accumulators to warp-private smem region, reset accs
            #pragma unroll
            for (int mt = 0; mt < 2; mt++)
                #pragma unroll
                for (int nt = 0; nt < 8; nt++) {
                    int r0 = m0 + mt * 16 + g, cc = n0 + nt * 8 + 2 * tg;
                    *(float2*)&stage[(size_t)r0 * G1_STRIDE + cc] =
                        make_float2(acc[mt][nt][0], acc[mt][nt][1]);
                    *(float2*)&stage[(size_t)(r0 + 8) * G1_STRIDE + cc] =
                        make_float2(acc[mt][nt][2], acc[mt][nt][3]);
                    acc[mt][nt][0] = 0.f; acc[mt][nt][1] = 0.f;
                    acc[mt][nt][2] = 0.f; acc[mt][nt][3] = 0.f;
                }
        }
        __syncthreads();                           // stage (c-1)%3 now reusable by all
        if (c + 2 < NCHT) issue(c + 2);
    }

    // ---- fused epilogue: G1 from smem, G2 in regs (identical to R8) ----
    const float c1 = g_c1, c2 = g_c2;
    const float OFFW = (float)(1.0 / ((double)BHALF * (double)(BHALF - 1)));
    const float NEGW = (float)(-1.0 / ((double)BHALF * (double)BHALF));

    float s1i[4], s2i[4];
    #pragma unroll
    for (int mt = 0; mt < 2; mt++)
        #pragma unroll
        for (int pr = 0; pr < 2; pr++) {
            int gi = Ibase + m0 + mt * 16 + pr * 8 + g;
            s1i[mt * 2 + pr] = g_sq1[gi];
            s2i[mt * 2 + pr] = g_sq2[gi];
        }
    float s1j[16], s2j[16];
    #pragma unroll
    for (int nt = 0; nt < 8; nt++)
        #pragma unroll
        for (int e = 0; e < 2; e++) {
            int gj = Jbase + n0 + nt * 8 + 2 * tg + e;
            s1j[nt * 2 + e] = g_sq1[gj];
            s2j[nt * 2 + e] = g_sq2[gj];
        }

    float local = 0.f;
    #pragma unroll
    for (int mt = 0; mt < 2; mt++)
        #pragma unroll
        for (int pr = 0; pr < 2; pr++) {
            int gi = Ibase + m0 + mt * 16 + pr * 8 + g;
            #pragma unroll
            for (int nt = 0; nt < 8; nt++) {
                int r0 = m0 + mt * 16 + pr * 8 + g, cc = n0 + nt * 8 + 2 * tg;
                float2 g1v = *(float2*)&stage[(size_t)r0 * G1_STRIDE + cc];
                #pragma unroll
                for (int e = 0; e < 2; e++) {
                    int gj = Jbase + cc + e;
                    float gram1 = e ? g1v.y : g1v.x;
                    float gram2 = acc[mt][nt][pr * 2 + e];
                    float l2a = fmaxf(s1i[mt * 2 + pr] + s1j[nt * 2 + e] - 2.f * gram1, 0.f);
                    float ex = __expf(-l2a * c1);
                    float k1 = ex; ex *= ex; k1 += ex; ex *= ex; k1 += ex;
                    ex *= ex; k1 += ex; ex *= ex; k1 += ex;
                    float l2b = fmaxf(s2i[mt * 2 + pr] + s2j[nt * 2 + e] - 2.f * gram2, 0.f);
                    ex = __expf(-l2b * c2);
                    float k2 = ex; ex *= ex; k2 += ex; ex *= ex; k2 += ex;
                    ex *= ex; k2 += ex; ex *= ex; k2 += ex;
                    if (gi > gj) {
                        float w = ((gi < BHALF) == (gj < BHALF)) ? OFFW : NEGW;
                        local += 2.f * w * k1 * k2;
                    }
                }
            }
        }

    #pragma unroll
    for (int o = 16; o > 0; o >>= 1) local += __shfl_down_sync(0xffffffffu, local, o);
    float* red = (float*)(smem + RED_OFF);
    if (lane == 0) red[wid] = local;
    __syncthreads();
    if (tid == 0) {
        float ssum = 0.f;
        #pragma unroll
        for (int wgi = 0; wgi < 8; wgi++) ssum += red[wgi];
        atomicAdd(&g_acc, (double)ssum);
    }
}

// ---------------- finalize ----------------
__global__ void finalize_kernel(float* out) {
    out[0] = (float)(g_acc + 2.0 / (double)(BHALF - 1));
}

extern "C" void kernel_launch(void* const* d_in, const int* in_sizes, int n_in,
                              void* d_out, int out_size) {
    const float* z1s = (const float*)d_in[0];
    const float* z1t = (const float*)d_in[1];
    const float* z2s = (const float*)d_in[2];
    const float* z2t = (const float*)d_in[3];
    float* out = (float*)d_out;

    cudaFuncSetAttribute(jmmd_mma, cudaFuncAttributeMaxDynamicSharedMemorySize, SMEM_TOTAL);

    init_kernel<<<(D1 + 255) / 256, 256>>>();
    rowsq_kernel<<<2 * NROWS, 128>>>(z1s, z1t, z2s, z2t);
    colsum_partial<<<((D1 + D2) / 256) * 16, 256>>>(z1s, z1t, z2s, z2t);
    tsum_kernel<<<(D1 + D2) / 256, 256>>>();
    bw_kernel<<<1, 1>>>();
    jmmd_mma<<<GRID_TILES, 256, SMEM_TOTAL>>>(z1s, z1t, z2s, z2t);
    finalize_kernel<<<1, 1>>>(out);
}

// round 16
// speedup vs baseline: 3.1991x; 1.4377x over previous
#include <cuda_runtime.h>
#include <cstdint>
#include <math.h>

// ---------------- problem constants ----------------
#define BHALF 2048
#define NROWS 4096
#define D1    4096
#define D2    2048

// ---------------- tiling ----------------
#define TILE  128                   // CTA tile: 128 x 128
#define BK    64                    // k per chunk (floats) = 256B per row
#define NSTAGE 3
#define NCH1  (D1 / BK)             // 64
#define NCH2  (D2 / BK)             // 32
#define NCHT  (NCH1 + NCH2)         // 96
#define GRID_TILES (32 * 33 / 2)    // 528 triangular tiles

// smem layout (bytes). Rows padded to 272B (17 x 16B -> ldmatrix conflict-free,
// 272 mod 128 = 16, same geometry as the proven 144-pad at BK=32).
#define RSB       272u
#define ATILE_B   (128u * RSB)             // 34816
#define STAGE_B   (2u * ATILE_B)           // 69632 per stage (A + B)
#define MB_FULL(s) (16u + 8u*(s))
#define SM_A(s)   (1024u + (s) * STAGE_B)
#define SM_B(s)   (SM_A(s) + ATILE_B)
#define RED_OFF   (1024u + NSTAGE * STAGE_B)   // 209920
#define SMEM_TOTAL (RED_OFF + 64u)             // 209984
#define CHUNK_BYTES 65536u          // 256 rows x 256B per chunk

// ---------------- device scratch ----------------
__device__ float  g_sq1[NROWS];
__device__ float  g_sq2[NROWS];
__device__ float  g_cs1[D1];
__device__ float  g_cs2[D2];
__device__ double g_S1, g_S2, g_T1, g_T2;
__device__ float  g_c1, g_c2;
__device__ double g_acc;

// ---------------- asm helpers (baseline sm_90-level PTX only) ----------------
__device__ __forceinline__ uint32_t smem_u32(const void* p) {
    uint32_t a;
    asm("{ .reg .u64 t; cvta.to.shared.u64 t, %1; cvt.u32.u64 %0, t; }" : "=r"(a) : "l"(p));
    return a;
}
__device__ __forceinline__ void mbar_init(uint32_t a, uint32_t cnt) {
    asm volatile("mbarrier.init.shared.b64 [%0], %1;" :: "r"(a), "r"(cnt) : "memory");
}
__device__ __forceinline__ void mbar_expect_tx(uint32_t a, uint32_t bytes) {
    asm volatile("mbarrier.arrive.expect_tx.shared.b64 _, [%0], %1;"
                 :: "r"(a), "r"(bytes) : "memory");
}
__device__ __forceinline__ void mbar_wait(uint32_t a, uint32_t parity) {
    uint32_t done;
    asm volatile("{\n\t.reg .pred p;\n\t"
        "mbarrier.try_wait.parity.acquire.cta.shared::cta.b64 p, [%1], %2;\n\t"
        "selp.b32 %0, 1, 0, p;\n\t}"
        : "=r"(done) : "r"(a), "r"(parity) : "memory");
    if (!done) {
        asm volatile("{\n\t.reg .pred P1;\n\t"
            "WL%=:\n\t"
            "mbarrier.try_wait.parity.acquire.cta.shared::cta.b64 P1, [%0], %1, 0x989680;\n\t"
            "@P1 bra.uni WD%=;\n\t"
            "bra.uni WL%=;\n\t"
            "WD%=:\n\t}"
            :: "r"(a), "r"(parity) : "memory");
    }
}
#define BULK_CP256(dst, src, mbar) \
    asm volatile("cp.async.bulk.shared::cluster.global.mbarrier::complete_tx::bytes " \
                 "[%0], [%1], %2, [%3];" \
                 :: "r"(dst), "l"(src), "r"(256u), "r"(mbar) : "memory")

#define LDSM4(r, addr) \
    asm volatile("ldmatrix.sync.aligned.m8n8.x4.shared.b16 {%0,%1,%2,%3}, [%4];" \
        : "=r"((r)[0]), "=r"((r)[1]), "=r"((r)[2]), "=r"((r)[3]) : "r"(addr))

#define MMA_TF32(d, a, b) \
    asm volatile("mma.sync.aligned.m16n8k8.row.col.f32.tf32.tf32.f32 " \
        "{%0,%1,%2,%3}, {%4,%5,%6,%7}, {%8,%9}, {%0,%1,%2,%3};" \
        : "+f"((d)[0]), "+f"((d)[1]), "+f"((d)[2]), "+f"((d)[3]) \
        : "r"((a)[0]), "r"((a)[1]), "r"((a)[2]), "r"((a)[3]), \
          "r"((b)[0]), "r"((b)[1]))

// ---------------- prepass kernels (unchanged, proven) ----------------
__global__ void init_kernel() {
    int idx = blockIdx.x * blockDim.x + threadIdx.x;
    if (idx < D1) g_cs1[idx] = 0.f;
    if (idx < D2) g_cs2[idx] = 0.f;
    if (idx == 0) { g_S1 = 0.0; g_S2 = 0.0; g_T1 = 0.0; g_T2 = 0.0; g_acc = 0.0; }
}

__global__ void rowsq_kernel(const float* __restrict__ z1s, const float* __restrict__ z1t,
                             const float* __restrict__ z2s, const float* __restrict__ z2t) {
    int task  = blockIdx.x;
    int which = task >> 12;
    int row   = task & (NROWS - 1);
    const float* p;
    int d4;
    if (which == 0) {
        d4 = D1 / 4;
        p = (row < BHALF) ? z1s + (size_t)row * D1 : z1t + (size_t)(row - BHALF) * D1;
    } else {
        d4 = D2 / 4;
        p = (row < BHALF) ? z2s + (size_t)row * D2 : z2t + (size_t)(row - BHALF) * D2;
    }
    const float4* p4 = (const float4*)p;
    float s = 0.f;
    for (int k = threadIdx.x; k < d4; k += blockDim.x) {
        float4 v = p4[k];
        s += v.x * v.x + v.y * v.y + v.z * v.z + v.w * v.w;
    }
    __shared__ float sh[4];
    #pragma unroll
    for (int o = 16; o > 0; o >>= 1) s += __shfl_down_sync(0xffffffffu, s, o);
    if ((threadIdx.x & 31) == 0) sh[threadIdx.x >> 5] = s;
    __syncthreads();
    if (threadIdx.x == 0) {
        float t = sh[0] + sh[1] + sh[2] + sh[3];
        if (which == 0) { g_sq1[row] = t; atomicAdd(&g_S1, (double)t); }
        else            { g_sq2[row] = t; atomicAdd(&g_S2, (double)t); }
    }
}

__global__ void colsum_partial(const float* __restrict__ z1s, const float* __restrict__ z1t,
                               const float* __restrict__ z2s, const float* __restrict__ z2t) {
    const int colBlocks = (D1 + D2) / 256;
    int cb    = blockIdx.x % colBlocks;
    int chunk = blockIdx.x / colBlocks;
    int idx   = cb * 256 + threadIdx.x;
    int r0    = chunk * 256;
    float cs = 0.f;
    if (idx < D1) {
        const float* p = (r0 < BHALF) ? z1s + (size_t)r0 * D1 + idx
                                      : z1t + (size_t)(r0 - BHALF) * D1 + idx;
        #pragma unroll 4
        for (int r = 0; r < 256; r++) cs += p[(size_t)r * D1];
        atomicAdd(&g_cs1[idx], cs);
    } else {
        int k = idx - D1;
        const float* p = (r0 < BHALF) ? z2s + (size_t)r0 * D2 + k
                                      : z2t + (size_t)(r0 - BHALF) * D2 + k;
        #pragma unroll 4
        for (int r = 0; r < 256; r++) cs += p[(size_t)r * D2];
        atomicAdd(&g_cs2[k], cs);
    }
}

__global__ void tsum_kernel() {
    int idx = blockIdx.x * blockDim.x + threadIdx.x;
    double v;
    double* dst;
    if (idx < D1) { float c = g_cs1[idx];       v = (double)c * c; dst = &g_T1; }
    else          { float c = g_cs2[idx - D1];  v = (double)c * c; dst = &g_T2; }
    #pragma unroll
    for (int o = 16; o > 0; o >>= 1)
        v += __shfl_down_sync(0xffffffffu, v, o);
    if ((threadIdx.x & 31) == 0) atomicAdd(dst, v);
}

__global__ void bw_kernel() {
    double nn = (double)NROWS * (double)(NROWS - 1);
    double sum1 = 2.0 * (double)NROWS * g_S1 - 2.0 * g_T1;
    double sum2 = 2.0 * (double)NROWS * g_S2 - 2.0 * g_T2;
    g_c1 = (float)(1.0 / (16.0 * (sum1 / nn / 4.0)));
    g_c2 = (float)(1.0 / (16.0 * (sum2 / nn / 4.0)));
}

// ---------------- main kernel: tf32 mma.sync dual-Gram, 256B bulk loads ----------
__global__ __launch_bounds__(256, 1)
void jmmd_mma(const float* __restrict__ z1s, const float* __restrict__ z1t,
              const float* __restrict__ z2s, const float* __restrict__ z2t) {
    extern __shared__ char smem[];
    uint32_t sb = smem_u32(smem);
    int tid = threadIdx.x, wid = tid >> 5, lane = tid & 31;

    // triangular unrank: tile (I, J), I >= J, both over 32 tiles of 128
    int rem = blockIdx.x, I = 0;
    while (rem >= I + 1) { rem -= I + 1; I++; }
    int J = rem;
    int Ibase = I * TILE, Jbase = J * TILE;

    const float* a1 = (Ibase < BHALF) ? z1s + (size_t)Ibase * D1 : z1t + (size_t)(Ibase - BHALF) * D1;
    const float* b1 = (Jbase < BHALF) ? z1s + (size_t)Jbase * D1 : z1t + (size_t)(Jbase - BHALF) * D1;
    const float* a2 = (Ibase < BHALF) ? z2s + (size_t)Ibase * D2 : z2t + (size_t)(Ibase - BHALF) * D2;
    const float* b2 = (Jbase < BHALF) ? z2s + (size_t)Jbase * D2 : z2t + (size_t)(Jbase - BHALF) * D2;

    int m0 = (wid & 3) * 32;        // warp sub-tile 32 (M) x 64 (N)
    int n0 = (wid >> 2) * 64;

    // BOTH Gram accumulators resident in registers (no G1 smem staging)
    float acc1[2][8][4], acc2[2][8][4];
    #pragma unroll
    for (int mt = 0; mt < 2; mt++)
        #pragma unroll
        for (int nt = 0; nt < 8; nt++)
            #pragma unroll
            for (int r = 0; r < 4; r++) { acc1[mt][nt][r] = 0.f; acc2[mt][nt][r] = 0.f; }

    if (tid == 0) {
        #pragma unroll
        for (int s = 0; s < NSTAGE; s++) mbar_init(sb + MB_FULL(s), 1);
    }
    __syncthreads();

    // ---- loader: ONE 256B cp.async.bulk per thread per chunk (row = tid) ----
    int lrow  = tid & 127;
    int isB   = tid >> 7;
    uint32_t dstoff = (uint32_t)lrow * RSB;
    auto issue = [&](int c) {
        int s = c % NSTAGE;                      // FIX (R15 bug): true modulo
        if (tid == 0) mbar_expect_tx(sb + MB_FULL(s), CHUNK_BYTES);
        const float* src;
        if (c < NCH1) src = (isB ? b1 : a1) + (size_t)lrow * D1 + c * BK;
        else          src = (isB ? b2 : a2) + (size_t)lrow * D2 + (c - NCH1) * BK;
        uint32_t dst = sb + (isB ? SM_B(s) : SM_A(s)) + dstoff;
        BULK_CP256(dst, src, sb + MB_FULL(s));
    };

    // ---- compute one BK=64 chunk into the given accumulator set ----
    auto compute = [&](int s, float (&acc)[2][8][4]) {
        uint32_t bufA = sb + SM_A(s), bufB = sb + SM_B(s);
        #pragma unroll
        for (int ks = 0; ks < 8; ks++) {          // 8 x K=8 steps = K 64
            uint32_t a[2][4];
            #pragma unroll
            for (int mt = 0; mt < 2; mt++) {
                uint32_t row = (uint32_t)(m0 + mt * 16 + (lane & 15));
                uint32_t col = (uint32_t)(ks * 32 + ((lane >> 4) << 4));
                LDSM4(a[mt], bufA + row * RSB + col);
            }
            uint32_t b[8][2];
            #pragma unroll
            for (int np = 0; np < 4; np++) {
                int q = lane >> 3;
                uint32_t row = (uint32_t)(n0 + np * 16 + (lane & 7) + ((q >> 1) << 3));
                uint32_t col = (uint32_t)(ks * 32 + ((q & 1) << 4));
                uint32_t r4[4];
                LDSM4(r4, bufB + row * RSB + col);
                b[2 * np][0] = r4[0]; b[2 * np][1] = r4[1];
                b[2 * np + 1][0] = r4[2]; b[2 * np + 1][1] = r4[3];
            }
            #pragma unroll
            for (int mt = 0; mt < 2; mt++)
                #pragma unroll
                for (int nt = 0; nt < 8; nt++)
                    MMA_TF32(acc[mt][nt], a[mt], b[nt]);
        }
    };

    // ---- pipelined main loop (3 stages) ----
    issue(0); issue(1);
    int ph = 0, puse = 0, s = 0;
    for (int c = 0; c < NCHT; c++) {
        mbar_wait(sb + MB_FULL(s), ph);
        if (++puse == NSTAGE) { puse = 0; ph ^= 1; }
        if (c < NCH1) compute(s, acc1);
        else          compute(s, acc2);
        __syncthreads();                      // all warps past compute -> prev stage free
        if (c + 2 < NCHT) issue(c + 2);
        if (++s == NSTAGE) s = 0;
    }

    // ---- fused epilogue: both Grams straight from registers ----
    const float c1 = g_c1, c2 = g_c2;
    const float OFFW = (float)(1.0 / ((double)BHALF * (double)(BHALF - 1)));
    const float NEGW = (float)(-1.0 / ((double)BHALF * (double)BHALF));
    int g = lane >> 2, tg = lane & 3;

    float s1i[4], s2i[4];
    #pragma unroll
    for (int mt = 0; mt < 2; mt++)
        #pragma unroll
        for (int pr = 0; pr < 2; pr++) {
            int gi = Ibase + m0 + mt * 16 + pr * 8 + g;
            s1i[mt * 2 + pr] = g_sq1[gi];
            s2i[mt * 2 + pr] = g_sq2[gi];
        }
    float s1j[16], s2j[16];
    #pragma unroll
    for (int nt = 0; nt < 8; nt++)
        #pragma unroll
        for (int e = 0; e < 2; e++) {
            int gj = Jbase + n0 + nt * 8 + 2 * tg + e;
            s1j[nt * 2 + e] = g_sq1[gj];
            s2j[nt * 2 + e] = g_sq2[gj];
        }

    float local = 0.f;
    #pragma unroll
    for (int mt = 0; mt < 2; mt++)
        #pragma unroll
        for (int pr = 0; pr < 2; pr++) {
            int gi = Ibase + m0 + mt * 16 + pr * 8 + g;
            #pragma unroll
            for (int nt = 0; nt < 8; nt++) {
                #pragma unroll
                for (int e = 0; e < 2; e++) {
                    int gj = Jbase + n0 + nt * 8 + 2 * tg + e;
                    float gram1 = acc1[mt][nt][pr * 2 + e];
                    float gram2 = acc2[mt][nt][pr * 2 + e];
                    float l2a = fmaxf(s1i[mt * 2 + pr] + s1j[nt * 2 + e] - 2.f * gram1, 0.f);
                    float ex = __expf(-l2a * c1);
                    float k1 = ex; ex *= ex; k1 += ex; ex *= ex; k1 += ex;
                    ex *= ex; k1 += ex; ex *= ex; k1 += ex;
                    float l2b = fmaxf(s2i[mt * 2 + pr] + s2j[nt * 2 + e] - 2.f * gram2, 0.f);
                    ex = __expf(-l2b * c2);
                    float k2 = ex; ex *= ex; k2 += ex; ex *= ex; k2 += ex;
                    ex *= ex; k2 += ex; ex *= ex; k2 += ex;
                    if (gi > gj) {
                        float w = ((gi < BHALF) == (gj < BHALF)) ? OFFW : NEGW;
                        local += 2.f * w * k1 * k2;
                    }
                }
            }
        }

    #pragma unroll
    for (int o = 16; o > 0; o >>= 1) local += __shfl_down_sync(0xffffffffu, local, o);
    float* red = (float*)(smem + RED_OFF);
    if (lane == 0) red[wid] = local;
    __syncthreads();
    if (tid == 0) {
        float ssum = 0.f;
        #pragma unroll
        for (int wgi = 0; wgi < 8; wgi++) ssum += red[wgi];
        atomicAdd(&g_acc, (double)ssum);
    }
}

// ---------------- finalize ----------------
__global__ void finalize_kernel(float* out) {
    out[0] = (float)(g_acc + 2.0 / (double)(BHALF - 1));
}

extern "C" void kernel_launch(void* const* d_in, const int* in_sizes, int n_in,
                              void* d_out, int out_size) {
    const float* z1s = (const float*)d_in[0];
    const float* z1t = (const float*)d_in[1];
    const float* z2s = (const float*)d_in[2];
    const float* z2t = (const float*)d_in[3];
    float* out = (float*)d_out;

    cudaFuncSetAttribute(jmmd_mma, cudaFuncAttributeMaxDynamicSharedMemorySize, SMEM_TOTAL);

    init_kernel<<<(D1 + 255) / 256, 256>>>();
    rowsq_kernel<<<2 * NROWS, 128>>>(z1s, z1t, z2s, z2t);
    colsum_partial<<<((D1 + D2) / 256) * 16, 256>>>(z1s, z1t, z2s, z2t);
    tsum_kernel<<<(D1 + D2) / 256, 256>>>();
    bw_kernel<<<1, 1>>>();
    jmmd_mma<<<GRID_TILES, 256, SMEM_TOTAL>>>(z1s, z1t, z2s, z2t);
    finalize_kernel<<<1, 1>>>(out);
}